// round 15
// baseline (speedup 1.0000x reference)
#include <cuda_runtime.h>

// MaxAssigner2D, fused single kernel, smem-resident xc + halo handoff:
//   Block b streams channel-max of its 8-row strip into SMEM (bottom 2 rows
//   also to the gmem halo buffer for block b+1), publishes flag[b], waits on
//   flag[b-1], then applies the 7-tap stencil
//   {(0,0),(-1,0),(-2,0),(0,-1),(0,-2),(-1,-1),(-2,-2)}  (out-of-image = 0).

#define BATCH 16
#define HGT   512
#define WID   512
#define CH    32
#define NPIX  (BATCH * HGT * WID)   // 4,194,304

#define NT    256
#define RPB   8                     // rows per block
#define PPB   (RPB * WID)           // 4096 pixels per strip
#define NBLK  (NPIX / PPB)          // 1024 blocks -> ONE resident wave
#define ITERS (PPB / (NT / 8))      // 128, exact
#define BPI   (HGT / RPB)           // 64 blocks per image
#define NQUAD (WID / 4)             // 128
#define DATA0 4                     // first data col in smem row (16B aligned)
#define SW    520                   // smem row stride (floats)

__device__ float g_halo[NBLK * 2 * WID];   // 4 MB: per strip, its rows 6,7
__device__ int   g_flag[NBLK];             // strip-ready flags (self-resetting)

__global__ void __launch_bounds__(NT)
fused_kernel(const float* __restrict__ x, float* __restrict__ out)
{
    __shared__ float s[RPB * SW];   // 16,640 B: own strip's xc, zero left halo

    const int t   = threadIdx.x;
    const int b   = blockIdx.x;
    const int g   = t >> 3;           // pixel-group within block (0..31)
    const int chq = t & 7;            // float4 within 32 channels

    // zero left-halo cols (DATA0-2, DATA0-1) of all 8 smem rows
    if (t < RPB * 2) s[(t >> 1) * SW + 2 + (t & 1)] = 0.0f;

    // ---- streaming channel-max of own strip (R13/R14 body) ------------------
    const size_t pix0 = (size_t)b * PPB;
    const float4* src = (const float4*)(x + pix0 * CH) + chq;
    float* halo_out = g_halo + (size_t)b * 2 * WID;

    #pragma unroll 8
    for (int it = 0; it < ITERS; it++) {
        const int p = it * 32 + g;                  // 0..4095, row-major
        const float4 d = __ldg(src + (size_t)p * (CH / 4));
        float v = fmaxf(fmaxf(d.x, d.y), fmaxf(d.z, d.w));
        v = fmaxf(v, __shfl_xor_sync(0xffffffffu, v, 1));
        v = fmaxf(v, __shfl_xor_sync(0xffffffffu, v, 2));
        v = fmaxf(v, __shfl_xor_sync(0xffffffffu, v, 4));
        if (chq == 0) {
            s[(p >> 9) * SW + DATA0 + (p & 511)] = v;
            if (p >= (RPB - 2) * WID) halo_out[p - (RPB - 2) * WID] = v; // rows 6,7
        }
    }

    // ---- publish own halo, then acquire predecessor's ----------------------
    __threadfence();
    __syncthreads();
    if (t == 0) {
        atomicExch(&g_flag[b], 1);            // publish BEFORE waiting
        if ((b % BPI) != 0) {
            while (atomicAdd(&g_flag[b - 1], 0) == 0) { }
            atomicExch(&g_flag[b - 1], 0);    // reset for next graph replay
            __threadfence();                  // acquire
        } else if (b > 0) {
            atomicExch(&g_flag[b - 1], 0);    // never waited on; reset
        }
    }
    __syncthreads();

    // ---- stencil own 8 rows (1024 quads, 4/thread) --------------------------
    const int  img     = b / BPI;
    const int  hh      = (b % BPI) * RPB;
    const bool hasPrev = (b % BPI) != 0;
    const float* hal   = g_halo + (size_t)(b - 1) * 2 * WID;  // prev rows 6,7
    float4* out_img    = (float4*)(out + (size_t)img * HGT * WID);

    const float4 z4 = make_float4(0.f, 0.f, 0.f, 0.f);
    const float2 z2 = make_float2(0.f, 0.f);

    #pragma unroll
    for (int i = 0; i < 4; i++) {
        const int qq = i * NT + t;        // 0..1023
        const int r  = qq >> 7;           // 0..7 (warp-uniform)
        const int q  = qq & 127;
        const int h  = hh + r;

        // row h: own smem (left halo cols are zero-padded, no predicates)
        const float* pA = s + r * SW + DATA0 + 4 * q;
        const float4 a  = *(const float4*)pA;
        const float  la1 = pA[-1], la2 = pA[-2];

        float4 bv; float lb1;             // row h-1
        float4 cv; float lc1, lc2;        // row h-2
        if (r >= 2) {
            const float* pB = pA - SW;
            const float* pC = pB - SW;
            bv = *(const float4*)pB; lb1 = pB[-1];
            cv = *(const float4*)pC; lc1 = pC[-1]; lc2 = pC[-2];
        } else if (r == 1) {
            const float* pB = s + DATA0 + 4 * q;      // own row 0
            bv = *(const float4*)pB; lb1 = pB[-1];
            if (hasPrev) {                             // prev row 7 = halo slot 1
                const float* C = hal + WID;
                cv = __ldg((const float4*)(C + 4 * q));
                const float2 lc = q ? __ldg((const float2*)(C + 4 * q - 2)) : z2;
                lc2 = lc.x; lc1 = lc.y;
            } else { cv = z4; lc1 = lc2 = 0.f; }
        } else {                                       // r == 0
            if (hasPrev) {
                const float* B = hal + WID;            // prev row 7 (h-1)
                const float* C = hal;                  // prev row 6 (h-2)
                bv = __ldg((const float4*)(B + 4 * q));
                lb1 = q ? __ldg(B + 4 * q - 1) : 0.f;
                cv = __ldg((const float4*)(C + 4 * q));
                const float2 lc = q ? __ldg((const float2*)(C + 4 * q - 2)) : z2;
                lc2 = lc.x; lc1 = lc.y;
            } else { bv = z4; cv = z4; lb1 = lc1 = lc2 = 0.f; }
        }

        // taps per col j: (0,j)(0,j-1)(0,j-2) | (-1,j)(-1,j-1) | (-2,j)(-2,j-2)
        float4 m;
        m.x = fmaxf(fmaxf(fmaxf(a.x, la1), fmaxf(la2, bv.x)),
                    fmaxf(lb1,  fmaxf(cv.x, lc2)));
        m.y = fmaxf(fmaxf(fmaxf(a.y, a.x), fmaxf(la1, bv.y)),
                    fmaxf(bv.x, fmaxf(cv.y, lc1)));
        m.z = fmaxf(fmaxf(fmaxf(a.z, a.y), fmaxf(a.x, bv.z)),
                    fmaxf(bv.y, fmaxf(cv.z, cv.x)));
        m.w = fmaxf(fmaxf(fmaxf(a.w, a.z), fmaxf(a.y, bv.w)),
                    fmaxf(bv.z, fmaxf(cv.w, cv.y)));

        out_img[(size_t)h * NQUAD + q] = m;
    }
}

extern "C" void kernel_launch(void* const* d_in, const int* in_sizes, int n_in,
                              void* d_out, int out_size)
{
    (void)in_sizes; (void)n_in; (void)out_size;
    const float* x = (const float*)d_in[0];
    float* out = (float*)d_out;

    fused_kernel<<<NBLK, NT>>>(x, out);
}

// round 16
// speedup vs baseline: 1.0468x; 1.0468x over previous
#include <cuda_runtime.h>

// MaxAssigner2D, fused single kernel, smem-resident xc + halo handoff (R14
// config: RPB=4, 2048 blocks) with a PURE streaming loop:
//   Block b streams channel-max of its 4-row strip into SMEM (no conditionals
//   in the hot loop), then writes the bottom 2 rows to the gmem halo buffer
//   with one STG.128 per thread, publishes flag[b], waits on flag[b-1], and
//   applies the 7-tap stencil {(0,0),(-1,0),(-2,0),(0,-1),(0,-2),(-1,-1),
//   (-2,-2)} to its own 4 rows (out-of-image taps = 0).

#define BATCH 16
#define HGT   512
#define WID   512
#define CH    32
#define NPIX  (BATCH * HGT * WID)   // 4,194,304

#define NT    256
#define RPB   4                     // rows per block
#define PPB   (RPB * WID)           // 2048 pixels per strip
#define NBLK  (NPIX / PPB)          // 2048 blocks
#define ITERS (PPB / (NT / 8))      // 64, exact
#define BPI   (HGT / RPB)           // 128 blocks per image
#define NQUAD (WID / 4)             // 128
#define DATA0 4                     // first data col in smem row (16B aligned)
#define SW    520                   // smem row stride (floats)

__device__ float g_halo[NBLK * 2 * WID];   // 8 MB: per strip, its rows 2,3
__device__ int   g_flag[NBLK];             // strip-ready flags (self-resetting)

__global__ void __launch_bounds__(NT)
fused_kernel(const float* __restrict__ x, float* __restrict__ out)
{
    __shared__ float s[RPB * SW];   // 8,320 B: own strip's xc, zero left halo

    const int t   = threadIdx.x;
    const int b   = blockIdx.x;
    const int g   = t >> 3;           // pixel-group within block (0..31)
    const int chq = t & 7;            // float4 within 32 channels

    // zero left-halo cols (DATA0-2, DATA0-1) of all 4 smem rows
    if (t < RPB * 2) s[(t >> 1) * SW + 2 + (t & 1)] = 0.0f;

    // ---- PURE streaming channel-max of own strip (no conditionals) ---------
    const size_t pix0 = (size_t)b * PPB;
    const float4* src = (const float4*)(x + pix0 * CH) + chq;

    #pragma unroll 8
    for (int it = 0; it < ITERS; it++) {
        const int p = it * 32 + g;                  // 0..2047, row-major
        const float4 d = __ldg(src + (size_t)p * (CH / 4));
        float v = fmaxf(fmaxf(d.x, d.y), fmaxf(d.z, d.w));
        v = fmaxf(v, __shfl_xor_sync(0xffffffffu, v, 1));
        v = fmaxf(v, __shfl_xor_sync(0xffffffffu, v, 2));
        v = fmaxf(v, __shfl_xor_sync(0xffffffffu, v, 4));
        if (chq == 0) s[(p >> 9) * SW + DATA0 + (p & 511)] = v;
    }
    __syncthreads();   // smem strip complete

    // ---- halo write: rows 2,3 from smem, one STG.128 per thread ------------
    {
        const int r  = 2 + (t >> 7);          // 2 or 3
        const int cq = t & 127;               // quad col
        const float4 hv = *(const float4*)(s + r * SW + DATA0 + 4 * cq);
        ((float4*)(g_halo + (size_t)b * 2 * WID))[(r - 2) * NQUAD + cq] = hv;
    }

    // ---- publish own halo, then acquire predecessor's ----------------------
    __threadfence();                      // order own halo stores before flag
    __syncthreads();                      // all threads' fences complete
    if (t == 0) {
        atomicExch(&g_flag[b], 1);            // publish BEFORE waiting
        if ((b % BPI) != 0) {
            while (atomicAdd(&g_flag[b - 1], 0) == 0) { }
            atomicExch(&g_flag[b - 1], 0);    // reset for next graph replay
            __threadfence();                  // acquire
        } else if (b > 0) {
            atomicExch(&g_flag[b - 1], 0);    // never waited on; reset
        }
    }
    __syncthreads();

    // ---- stencil own 4 rows (512 quads, 2/thread) ---------------------------
    const int  img     = b / BPI;
    const int  hh      = (b % BPI) * RPB;
    const bool hasPrev = (b % BPI) != 0;
    const float* hal   = g_halo + (size_t)(b - 1) * 2 * WID;  // prev rows 2,3
    float4* out_img    = (float4*)(out + (size_t)img * HGT * WID);

    const float4 z4 = make_float4(0.f, 0.f, 0.f, 0.f);
    const float2 z2 = make_float2(0.f, 0.f);

    #pragma unroll
    for (int i = 0; i < 2; i++) {
        const int qq = i * NT + t;        // 0..511
        const int r  = qq >> 7;           // 0..3 (warp-uniform)
        const int q  = qq & 127;
        const int h  = hh + r;

        // row h: own smem (left halo cols are zero-padded, no predicates)
        const float* pA = s + r * SW + DATA0 + 4 * q;
        const float4 a  = *(const float4*)pA;
        const float  la1 = pA[-1], la2 = pA[-2];

        float4 bv; float lb1;             // row h-1
        float4 cv; float lc1, lc2;        // row h-2
        if (r >= 2) {
            const float* pB = pA - SW;
            const float* pC = pB - SW;
            bv = *(const float4*)pB; lb1 = pB[-1];
            cv = *(const float4*)pC; lc1 = pC[-1]; lc2 = pC[-2];
        } else if (r == 1) {
            const float* pB = s + DATA0 + 4 * q;      // own row 0
            bv = *(const float4*)pB; lb1 = pB[-1];
            if (hasPrev) {                             // prev row 3 = halo slot 1
                const float* C = hal + WID;
                cv = __ldg((const float4*)(C + 4 * q));
                const float2 lc = q ? __ldg((const float2*)(C + 4 * q - 2)) : z2;
                lc2 = lc.x; lc1 = lc.y;
            } else { cv = z4; lc1 = lc2 = 0.f; }
        } else {                                       // r == 0
            if (hasPrev) {
                const float* B = hal + WID;            // prev row 3 (h-1)
                const float* C = hal;                  // prev row 2 (h-2)
                bv = __ldg((const float4*)(B + 4 * q));
                lb1 = q ? __ldg(B + 4 * q - 1) : 0.f;
                cv = __ldg((const float4*)(C + 4 * q));
                const float2 lc = q ? __ldg((const float2*)(C + 4 * q - 2)) : z2;
                lc2 = lc.x; lc1 = lc.y;
            } else { bv = z4; cv = z4; lb1 = lc1 = lc2 = 0.f; }
        }

        // taps per col j: (0,j)(0,j-1)(0,j-2) | (-1,j)(-1,j-1) | (-2,j)(-2,j-2)
        float4 m;
        m.x = fmaxf(fmaxf(fmaxf(a.x, la1), fmaxf(la2, bv.x)),
                    fmaxf(lb1,  fmaxf(cv.x, lc2)));
        m.y = fmaxf(fmaxf(fmaxf(a.y, a.x), fmaxf(la1, bv.y)),
                    fmaxf(bv.x, fmaxf(cv.y, lc1)));
        m.z = fmaxf(fmaxf(fmaxf(a.z, a.y), fmaxf(a.x, bv.z)),
                    fmaxf(bv.y, fmaxf(cv.z, cv.x)));
        m.w = fmaxf(fmaxf(fmaxf(a.w, a.z), fmaxf(a.y, bv.w)),
                    fmaxf(bv.z, fmaxf(cv.w, cv.y)));

        out_img[(size_t)h * NQUAD + q] = m;
    }
}

extern "C" void kernel_launch(void* const* d_in, const int* in_sizes, int n_in,
                              void* d_out, int out_size)
{
    (void)in_sizes; (void)n_in; (void)out_size;
    const float* x = (const float*)d_in[0];
    float* out = (float*)d_out;

    fused_kernel<<<NBLK, NT>>>(x, out);
}

// round 17
// speedup vs baseline: 1.0634x; 1.0159x over previous
#include <cuda_runtime.h>

// MaxAssigner2D, fused single kernel, smem-resident xc + EARLY halo publish:
//   Block b streams channel-max of its 4-row strip in two pure loops:
//     loop A: rows 2,3 -> smem + gmem halo (unconditional inline STG)
//     -> fence -> publish flag[b]            (successors unblocked halfway)
//     loop B: rows 0,1 -> smem only
//   then waits on flag[b-1] and applies the 7-tap stencil
//   {(0,0),(-1,0),(-2,0),(0,-1),(0,-2),(-1,-1),(-2,-2)}  (out-of-image = 0).

#define BATCH 16
#define HGT   512
#define WID   512
#define CH    32
#define NPIX  (BATCH * HGT * WID)   // 4,194,304

#define NT    256
#define RPB   4                     // rows per block
#define PPB   (RPB * WID)           // 2048 pixels per strip
#define NBLK  (NPIX / PPB)          // 2048 blocks
#define BPI   (HGT / RPB)           // 128 blocks per image
#define NQUAD (WID / 4)             // 128
#define DATA0 4                     // first data col in smem row (16B aligned)
#define SW    520                   // smem row stride (floats)

__device__ float g_halo[NBLK * 2 * WID];   // 8 MB: per strip, its rows 2,3
__device__ int   g_flag[NBLK];             // strip-ready flags (self-resetting)

__global__ void __launch_bounds__(NT)
fused_kernel(const float* __restrict__ x, float* __restrict__ out)
{
    __shared__ float s[RPB * SW];   // 8,320 B: own strip's xc, zero left halo

    const int t   = threadIdx.x;
    const int b   = blockIdx.x;
    const int g   = t >> 3;           // pixel-group within block (0..31)
    const int chq = t & 7;            // float4 within 32 channels

    // zero left-halo cols (DATA0-2, DATA0-1) of all 4 smem rows
    if (t < RPB * 2) s[(t >> 1) * SW + 2 + (t & 1)] = 0.0f;

    const size_t pix0 = (size_t)b * PPB;
    const float4* src = (const float4*)(x + pix0 * CH) + chq;
    float* halo_out = g_halo + (size_t)b * 2 * WID;

    // ---- loop A: rows 2,3 (pixels 1024..2047) -> smem + halo gmem ----------
    #pragma unroll 8
    for (int it = 32; it < 64; it++) {
        const int p = it * 32 + g;                  // 1024..2047
        const float4 d = __ldg(src + (size_t)p * (CH / 4));
        float v = fmaxf(fmaxf(d.x, d.y), fmaxf(d.z, d.w));
        v = fmaxf(v, __shfl_xor_sync(0xffffffffu, v, 1));
        v = fmaxf(v, __shfl_xor_sync(0xffffffffu, v, 2));
        v = fmaxf(v, __shfl_xor_sync(0xffffffffu, v, 4));
        if (chq == 0) {
            s[(p >> 9) * SW + DATA0 + (p & 511)] = v;
            halo_out[p - 2 * WID] = v;              // unconditional
        }
    }

    // ---- EARLY publish: halo rows are complete -----------------------------
    __threadfence();                  // drain halo stores (all threads)
    __syncthreads();
    if (t == 0) atomicExch(&g_flag[b], 1);   // publish BEFORE any waiting

    // ---- loop B: rows 0,1 (pixels 0..1023) -> smem only --------------------
    #pragma unroll 8
    for (int it = 0; it < 32; it++) {
        const int p = it * 32 + g;
        const float4 d = __ldg(src + (size_t)p * (CH / 4));
        float v = fmaxf(fmaxf(d.x, d.y), fmaxf(d.z, d.w));
        v = fmaxf(v, __shfl_xor_sync(0xffffffffu, v, 1));
        v = fmaxf(v, __shfl_xor_sync(0xffffffffu, v, 2));
        v = fmaxf(v, __shfl_xor_sync(0xffffffffu, v, 4));
        if (chq == 0) s[(p >> 9) * SW + DATA0 + (p & 511)] = v;
    }
    __syncthreads();   // smem strip complete

    // ---- acquire predecessor's halo -----------------------------------------
    if (t == 0) {
        if ((b % BPI) != 0) {
            while (atomicAdd(&g_flag[b - 1], 0) == 0) { }
            atomicExch(&g_flag[b - 1], 0);    // reset for next graph replay
            __threadfence();                  // acquire
        } else if (b > 0) {
            atomicExch(&g_flag[b - 1], 0);    // never waited on; reset (benign)
        }
    }
    __syncthreads();

    // ---- stencil own 4 rows (512 quads, 2/thread; R14-verified body) --------
    const int  img     = b / BPI;
    const int  hh      = (b % BPI) * RPB;
    const bool hasPrev = (b % BPI) != 0;
    const float* hal   = g_halo + (size_t)(b - 1) * 2 * WID;  // prev rows 2,3
    float4* out_img    = (float4*)(out + (size_t)img * HGT * WID);

    const float4 z4 = make_float4(0.f, 0.f, 0.f, 0.f);
    const float2 z2 = make_float2(0.f, 0.f);

    #pragma unroll
    for (int i = 0; i < 2; i++) {
        const int qq = i * NT + t;        // 0..511
        const int r  = qq >> 7;           // 0..3 (warp-uniform)
        const int q  = qq & 127;
        const int h  = hh + r;

        // row h: own smem (left halo cols are zero-padded, no predicates)
        const float* pA = s + r * SW + DATA0 + 4 * q;
        const float4 a  = *(const float4*)pA;
        const float  la1 = pA[-1], la2 = pA[-2];

        float4 bv; float lb1;             // row h-1
        float4 cv; float lc1, lc2;        // row h-2
        if (r >= 2) {
            const float* pB = pA - SW;
            const float* pC = pB - SW;
            bv = *(const float4*)pB; lb1 = pB[-1];
            cv = *(const float4*)pC; lc1 = pC[-1]; lc2 = pC[-2];
        } else if (r == 1) {
            const float* pB = s + DATA0 + 4 * q;      // own row 0
            bv = *(const float4*)pB; lb1 = pB[-1];
            if (hasPrev) {                             // prev row 3 = halo slot 1
                const float* C = hal + WID;
                cv = __ldg((const float4*)(C + 4 * q));
                const float2 lc = q ? __ldg((const float2*)(C + 4 * q - 2)) : z2;
                lc2 = lc.x; lc1 = lc.y;
            } else { cv = z4; lc1 = lc2 = 0.f; }
        } else {                                       // r == 0
            if (hasPrev) {
                const float* B = hal + WID;            // prev row 3 (h-1)
                const float* C = hal;                  // prev row 2 (h-2)
                bv = __ldg((const float4*)(B + 4 * q));
                lb1 = q ? __ldg(B + 4 * q - 1) : 0.f;
                cv = __ldg((const float4*)(C + 4 * q));
                const float2 lc = q ? __ldg((const float2*)(C + 4 * q - 2)) : z2;
                lc2 = lc.x; lc1 = lc.y;
            } else { bv = z4; cv = z4; lb1 = lc1 = lc2 = 0.f; }
        }

        // taps per col j: (0,j)(0,j-1)(0,j-2) | (-1,j)(-1,j-1) | (-2,j)(-2,j-2)
        float4 m;
        m.x = fmaxf(fmaxf(fmaxf(a.x, la1), fmaxf(la2, bv.x)),
                    fmaxf(lb1,  fmaxf(cv.x, lc2)));
        m.y = fmaxf(fmaxf(fmaxf(a.y, a.x), fmaxf(la1, bv.y)),
                    fmaxf(bv.x, fmaxf(cv.y, lc1)));
        m.z = fmaxf(fmaxf(fmaxf(a.z, a.y), fmaxf(a.x, bv.z)),
                    fmaxf(bv.y, fmaxf(cv.z, cv.x)));
        m.w = fmaxf(fmaxf(fmaxf(a.w, a.z), fmaxf(a.y, bv.w)),
                    fmaxf(bv.z, fmaxf(cv.w, cv.y)));

        out_img[(size_t)h * NQUAD + q] = m;
    }
}

extern "C" void kernel_launch(void* const* d_in, const int* in_sizes, int n_in,
                              void* d_out, int out_size)
{
    (void)in_sizes; (void)n_in; (void)out_size;
    const float* x = (const float*)d_in[0];
    float* out = (float*)d_out;

    fused_kernel<<<NBLK, NT>>>(x, out);
}